// round 15
// baseline (speedup 1.0000x reference)
#include <cuda_runtime.h>
#include <cuda_fp16.h>
#include <cstdint>

// Problem constants
#define NB    32
#define CLOC  512
#define HW2   196
#define NHW   6272
#define DGLB  2048
#define HIDN  256
#define EPSC  1e-10f
#define NJT   49                    // j-tiles of 128
#define NTILE (NJT * NB)            // 1568 tiles
#define NCTA  148                   // persistent CTAs

// Scratch (device globals; no allocation allowed)
__device__ float    g_hloc[NHW * HIDN];      // 6.4 MB
__device__ float    g_hglb[NB * HIDN];
__device__ float    g_scores[NB * NHW];      // 0.8 MB
// W2 in mma-fragment order: pair id = ((ks*4 + nw)*8 + nt)*32 + lane
__device__ uint2    g_W2f[16 * 4 * 8 * 32];  // 128 KB
// W1loc packed fp16: g_W1h[k2*256 + n] = half2(W1loc[2k2][n], W1loc[2k2+1][n])
__device__ uint32_t g_W1h[256 * 256];        // 256 KB

// ---------------------------------------------------------------------------
// helpers
// ---------------------------------------------------------------------------
__device__ __forceinline__ void mma16(float* c, const uint32_t* a,
                                      uint32_t b0, uint32_t b1) {
    asm volatile(
        "mma.sync.aligned.m16n8k16.row.col.f32.f16.f16.f32 "
        "{%0,%1,%2,%3}, {%4,%5,%6,%7}, {%8,%9}, {%0,%1,%2,%3};"
        : "+f"(c[0]), "+f"(c[1]), "+f"(c[2]), "+f"(c[3])
        : "r"(a[0]), "r"(a[1]), "r"(a[2]), "r"(a[3]), "r"(b0), "r"(b1));
}
__device__ __forceinline__ uint32_t smem_u32(const void* p) {
    uint32_t a;
    asm("{ .reg .u64 t; cvta.to.shared.u64 t, %1; cvt.u32.u64 %0, t; }" : "=r"(a) : "l"(p));
    return a;
}
__device__ __forceinline__ void cpa16(uint32_t dst, const void* src) {
    asm volatile("cp.async.ca.shared.global [%0], [%1], 16;" :: "r"(dst), "l"(src));
}
#define CPA_COMMIT() asm volatile("cp.async.commit_group;" ::: "memory")

// ---------------------------------------------------------------------------
// prep0 (grid 272, 256 thr):
//   blocks 0..255   -> h_glb: (i = bx>>3, o-chunk = (bx&7)*32), K/8
//   blocks 256..263 -> pack W2 into fp16 fragment order (g_W2f)
//   blocks 264..271 -> pack W1loc into fp16 [k2][n] half2 (g_W1h)
// ---------------------------------------------------------------------------
__global__ __launch_bounds__(256) void prep0_kernel(const float* __restrict__ gf,
                                                    const float* __restrict__ W1,
                                                    const float* __restrict__ b1,
                                                    const float* __restrict__ W2,
                                                    const float* __restrict__ W1loc) {
    const int tid = threadIdx.x;
    const int bx  = blockIdx.x;
    if (bx < 256) {
        __shared__ float red[256];
        const int i   = bx >> 3;
        const int o0  = (bx & 7) * 32;
        const int o   = o0 + (tid & 31);
        const int kq  = tid >> 5;            // 0..7
        const float* g = gf + i * DGLB + kq * 256;
        const float* w = W1 + (size_t)(kq * 256) * HIDN + o;
        float s0 = 0.f, s1 = 0.f;
        #pragma unroll 8
        for (int k = 0; k < 256; k += 2) {
            s0 += g[k]     * w[(size_t)k * HIDN];
            s1 += g[k + 1] * w[(size_t)(k + 1) * HIDN];
        }
        red[tid] = s0 + s1;
        __syncthreads();
        if (tid < 32) {
            float s = 0.f;
            #pragma unroll
            for (int q = 0; q < 8; q++) s += red[q * 32 + tid];
            g_hglb[i * HIDN + o0 + tid] = s + b1[o0 + tid];
        }
    } else if (bx < 264) {
        // W2 fragment pack
        const int pid0 = ((bx - 256) * 256 + tid) * 8;
        #pragma unroll
        for (int q = 0; q < 8; q++) {
            int id   = pid0 + q;
            int lane = id & 31;
            int nt   = (id >> 5) & 7;
            int nwp  = (id >> 8) & 3;
            int ks   = id >> 10;
            int gq   = lane >> 2, tg = lane & 3;
            int n    = nwp * 64 + nt * 8 + gq;
            int k0   = ks * 16 + 2 * tg;
            __half2 w0 = __floats2half2_rn(W2[(size_t)k0 * HIDN + n],
                                           W2[(size_t)(k0 + 1) * HIDN + n]);
            __half2 w1 = __floats2half2_rn(W2[(size_t)(k0 + 8) * HIDN + n],
                                           W2[(size_t)(k0 + 9) * HIDN + n]);
            g_W2f[id] = make_uint2(*(uint32_t*)&w0, *(uint32_t*)&w1);
        }
    } else {
        // W1loc pack: id -> k2 = id>>8, n = id&255
        const int id0 = ((bx - 264) * 256 + tid) * 32;
        #pragma unroll
        for (int q = 0; q < 32; q++) {
            int id = id0 + q;
            int k2 = id >> 8, n = id & 255;
            __half2 h = __floats2half2_rn(W1loc[(size_t)(2 * k2) * HIDN + n],
                                          W1loc[(size_t)(2 * k2 + 1) * HIDN + n]);
            g_W1h[id] = *(uint32_t*)&h;
        }
    }
}

// ---------------------------------------------------------------------------
// hloc kernel: 196 CTAs, 256 thr, BM=32, BK=64 x 8 chunks.
// B via cp.async from pre-packed g_W1h (2-deep group pipeline, zero regs);
// A gathered from NCHW via register prefetch. 8 warps = 1m x 8n (32m x 32n).
// mma kstep order identical to R14 -> bit-identical g_hloc.
// ---------------------------------------------------------------------------
#define HLA_HH  72                           // A stride in halves (36 words)
#define HLA_B   (32 * HLA_HH * 2)            // 4608 bytes per A buffer
#define HLB_W   264                          // B stride in words per k2-row
#define HLB_B   (32 * HLB_W * 4)             // 33792 bytes per B buffer
#define HL_SMEM (2 * HLA_B + 2 * HLB_B)      // 76800 bytes

__global__ __launch_bounds__(256) void hloc_kernel(const float* __restrict__ LF) {
    extern __shared__ char hsm[];
    const uint32_t sbase = smem_u32(hsm);
    const int tid = threadIdx.x;
    const int wid = tid >> 5, lid = tid & 31;
    const int g   = lid >> 2, tig = lid & 3;
    const int n0w = wid * 32;
    const int j0  = blockIdx.x * 32;

    // A build map: row = tid&31, akq = tid>>5 -> halves akq*8..akq*8+7
    const int arow = tid & 31;
    const int akq  = tid >> 5;
    const int j    = j0 + arow;
    const int n_   = j / HW2;
    const int pos  = j % HW2;
    const size_t abase = (size_t)n_ * CLOC * HW2 + pos;
    // B cp map: bn4 = tid&63, k2loc = (tid>>6) + 4r, r<8
    const int bn4 = tid & 63;
    const int bkb = tid >> 6;

    float acc[2][4][4];
    #pragma unroll
    for (int mt = 0; mt < 2; mt++)
        #pragma unroll
        for (int nt = 0; nt < 4; nt++)
            #pragma unroll
            for (int q = 0; q < 4; q++) acc[mt][nt][q] = 0.f;

    const uint32_t bs0 = sbase + 2 * HLA_B;

    // ---- prologue: cp.async B0 -> buf0, B1 -> buf1; build A0 ----
    #pragma unroll
    for (int r = 0; r < 8; r++) {
        int k2 = bkb + r * 4;
        cpa16(bs0 + k2 * (HLB_W * 4) + bn4 * 16,
              g_W1h + (size_t)k2 * 256 + bn4 * 4);
    }
    CPA_COMMIT();
    #pragma unroll
    for (int r = 0; r < 8; r++) {
        int k2 = bkb + r * 4;
        cpa16(bs0 + HLB_B + k2 * (HLB_W * 4) + bn4 * 16,
              g_W1h + (size_t)(32 + k2) * 256 + bn4 * 4);
    }
    CPA_COMMIT();
    {
        __half* A0 = (__half*)hsm;
        float f[8];
        #pragma unroll
        for (int q = 0; q < 8; q++)
            f[q] = LF[abase + (size_t)(akq * 8 + q) * HW2];
        __half2 h0 = __floats2half2_rn(f[0], f[1]);
        __half2 h1 = __floats2half2_rn(f[2], f[3]);
        __half2 h2 = __floats2half2_rn(f[4], f[5]);
        __half2 h3 = __floats2half2_rn(f[6], f[7]);
        *(uint4*)(A0 + arow * HLA_HH + akq * 8) =
            make_uint4(*(uint32_t*)&h0, *(uint32_t*)&h1,
                       *(uint32_t*)&h2, *(uint32_t*)&h3);
    }
    asm volatile("cp.async.wait_group 1;" ::: "memory");
    __syncthreads();

    for (int c = 0; c < 8; c++) {
        const int pb = c & 1, nb = pb ^ 1;
        const uint32_t* AsU = (const uint32_t*)(hsm + pb * HLA_B);
        const uint32_t* BsU = (const uint32_t*)(hsm + 2 * HLA_B + pb * HLB_B);

        // prefetch next chunk's A to registers
        float aR[8];
        if (c < 7) {
            const int kb = (c + 1) * 64;
            #pragma unroll
            for (int q = 0; q < 8; q++)
                aR[q] = LF[abase + (size_t)(kb + akq * 8 + q) * HW2];
        }

        // mma: 4 k16 steps
        #pragma unroll
        for (int s = 0; s < 4; s++) {
            const int kw = s * 8;
            uint32_t a[2][4];
            #pragma unroll
            for (int mt = 0; mt < 2; mt++) {
                int mr = mt * 16 + g;
                a[mt][0] = AsU[mr * 36 + kw + tig];
                a[mt][1] = AsU[(mr + 8) * 36 + kw + tig];
                a[mt][2] = AsU[mr * 36 + kw + tig + 4];
                a[mt][3] = AsU[(mr + 8) * 36 + kw + tig + 4];
            }
            #pragma unroll
            for (int nt = 0; nt < 4; nt++) {
                int nc = n0w + nt * 8 + g;
                uint32_t b0 = BsU[(s * 8 + tig) * HLB_W + nc];
                uint32_t b1 = BsU[(s * 8 + tig + 4) * HLB_W + nc];
                mma16(acc[0][nt], a[0], b0, b1);
                mma16(acc[1][nt], a[1], b0, b1);
            }
        }

        // store prefetched A into the other buffer
        if (c < 7) {
            __half* AN = (__half*)(hsm + nb * HLA_B);
            __half2 h0 = __floats2half2_rn(aR[0], aR[1]);
            __half2 h1 = __floats2half2_rn(aR[2], aR[3]);
            __half2 h2 = __floats2half2_rn(aR[4], aR[5]);
            __half2 h3 = __floats2half2_rn(aR[6], aR[7]);
            *(uint4*)(AN + arow * HLA_HH + akq * 8) =
                make_uint4(*(uint32_t*)&h0, *(uint32_t*)&h1,
                           *(uint32_t*)&h2, *(uint32_t*)&h3);
        }
        __syncthreads();                     // all warps done with pb buffers

        if (c < 6) {
            // cp.async B_{c+2} into the pb B-buffer
            uint32_t dst = bs0 + pb * HLB_B;
            #pragma unroll
            for (int r = 0; r < 8; r++) {
                int k2 = bkb + r * 4;
                cpa16(dst + k2 * (HLB_W * 4) + bn4 * 16,
                      g_W1h + (size_t)((c + 2) * 32 + k2) * 256 + bn4 * 4);
            }
            CPA_COMMIT();
            asm volatile("cp.async.wait_group 1;" ::: "memory");
            __syncthreads();
        } else if (c == 6) {
            asm volatile("cp.async.wait_group 0;" ::: "memory");
            __syncthreads();
        }
    }

    // epilogue: write fp32 h_loc
    #pragma unroll
    for (int mt = 0; mt < 2; mt++) {
        int row0 = j0 + mt * 16 + g;
        #pragma unroll
        for (int nt = 0; nt < 4; nt++) {
            int ncol = n0w + nt * 8 + 2 * tig;
            *(float2*)&g_hloc[(size_t)row0 * HIDN + ncol] =
                make_float2(acc[mt][nt][0], acc[mt][nt][1]);
            *(float2*)&g_hloc[(size_t)(row0 + 8) * HIDN + ncol] =
                make_float2(acc[mt][nt][2], acc[mt][nt][3]);
        }
    }
}

// ---------------------------------------------------------------------------
// PERSISTENT score kernel (UNCHANGED): 148 CTAs, 512 threads.
// ---------------------------------------------------------------------------
#define AS_STRH  72                                 // halves per A row (36 words)
#define AS_BYTES (128 * AS_STRH * 2)                // 18432
#define BCHUNK   32768
#define AS_OFF   0
#define BS_OFF   (2 * AS_BYTES)                     // 36864
#define B2_OFF   (BS_OFF + 4 * BCHUNK)              // 167936
#define W3_OFF   (B2_OFF + 1024)
#define RED_OFF  (W3_OFF + 1024)
#define SM_TOTAL (RED_OFF + 128 * 4 * 4)            // 172032

__global__ __launch_bounds__(512, 1) void score_mma(const float* __restrict__ b2,
                                                    const float* __restrict__ W3,
                                                    const float* __restrict__ b3p) {
    extern __shared__ char smem[];
    float* b2s = (float*)(smem + B2_OFF);
    float* w3s = (float*)(smem + W3_OFF);
    float* red = (float*)(smem + RED_OFF);
    const uint32_t sbase = smem_u32(smem);

    const int tid = threadIdx.x;
    const int wid = tid >> 5, lid = tid & 31;
    const int g   = lid >> 2, tig = lid & 3;
    const int m0w = (wid & 3) * 32;
    const int nw  = wid >> 2;
    const int n0w = nw * 64;

    {
        const char* bsrc = (const char*)g_W2f;
        #pragma unroll
        for (int cg2 = 0; cg2 < 4; cg2++) {
            #pragma unroll
            for (int r = 0; r < 4; r++) {
                int off = cg2 * BCHUNK + (tid + r * 512) * 16;
                cpa16(sbase + BS_OFF + off, bsrc + off);
            }
            CPA_COMMIT();
        }
    }

    if (tid < 256) { b2s[tid] = b2[tid]; w3s[tid] = W3[tid]; }
    const float b3v = b3p[0];

    const int k4   = tid & 15;
    const int mrow = tid >> 4;

    float acc[2][8][4];
    #pragma unroll
    for (int mt = 0; mt < 2; mt++)
        #pragma unroll
        for (int nt = 0; nt < 8; nt++)
            #pragma unroll
            for (int q = 0; q < 4; q++) acc[mt][nt][q] = 0.f;

    {
        const int t0 = blockIdx.x;
        const float* hl = g_hloc + (size_t)(t0 % NJT) * 128 * HIDN;
        const float* gb = g_hglb + (t0 / NJT) * HIDN;
        float4 gv = *(const float4*)(gb + k4 * 4);
        __half* As0 = (__half*)(smem + AS_OFF);
        #pragma unroll
        for (int r = 0; r < 4; r++) {
            int m = mrow + r * 32;
            float4 v = *(const float4*)(hl + (size_t)m * HIDN + k4 * 4);
            __half2 h01 = __floats2half2_rn(fmaxf(v.x + gv.x, 0.f), fmaxf(v.y + gv.y, 0.f));
            __half2 h23 = __floats2half2_rn(fmaxf(v.z + gv.z, 0.f), fmaxf(v.w + gv.w, 0.f));
            *(uint2*)(As0 + m * AS_STRH + k4 * 4) =
                make_uint2(*(uint32_t*)&h01, *(uint32_t*)&h23);
        }
        asm volatile("cp.async.wait_group 3;" ::: "memory");
        __syncthreads();
    }

    const uint2* BsP = (const uint2*)(smem + BS_OFF);
    int cg = 0;

    for (int t = blockIdx.x; t < NTILE; t += NCTA) {
        const int jt = t % NJT, ii = t / NJT;

        for (int c = 0; c < 4; c++) {
            const int pb = cg & 1, nb = pb ^ 1;
            const uint32_t* AsU = (const uint32_t*)(smem + AS_OFF + pb * AS_BYTES);

            const bool hn = (c < 3) || (t + NCTA < NTILE);
            float4 areg[4];
            float4 gvn;
            if (hn) {
                const int t2 = (c < 3) ? t : t + NCTA;
                const int c2 = (c < 3) ? c + 1 : 0;
                const float* hl2 = g_hloc + (size_t)(t2 % NJT) * 128 * HIDN;
                const float* gb2 = g_hglb + (t2 / NJT) * HIDN;
                const int kb2 = c2 * 64;
                gvn = *(const float4*)(gb2 + kb2 + k4 * 4);
                #pragma unroll
                for (int r = 0; r < 4; r++) {
                    int m = mrow + r * 32;
                    areg[r] = *(const float4*)(hl2 + (size_t)m * HIDN + kb2 + k4 * 4);
                }
            }

            #pragma unroll
            for (int kk = 0; kk < 4; kk++) {
                const int kw = kk * 8;
                const int ks = c * 4 + kk;
                uint32_t a[2][4];
                #pragma unroll
                for (int mt = 0; mt < 2; mt++) {
                    int mr = m0w + mt * 16 + g;
                    a[mt][0] = AsU[mr * 36 + kw + tig];
                    a[mt][1] = AsU[(mr + 8) * 36 + kw + tig];
                    a[mt][2] = AsU[mr * 36 + kw + tig + 4];
                    a[mt][3] = AsU[(mr + 8) * 36 + kw + tig + 4];
                }
                #pragma unroll
                for (int nt = 0; nt < 8; nt++) {
                    uint2 bw = BsP[((ks * 4 + nw) * 8 + nt) * 32 + lid];
                    mma16(acc[0][nt], a[0], bw.x, bw.y);
                    mma16(acc[1][nt], a[1], bw.x, bw.y);
                }
            }

            if (hn) {
                __half* AsN = (__half*)(smem + AS_OFF + nb * AS_BYTES);
                #pragma unroll
                for (int r = 0; r < 4; r++) {
                    int m = mrow + r * 32;
                    __half2 h01 = __floats2half2_rn(fmaxf(areg[r].x + gvn.x, 0.f),
                                                    fmaxf(areg[r].y + gvn.y, 0.f));
                    __half2 h23 = __floats2half2_rn(fmaxf(areg[r].z + gvn.z, 0.f),
                                                    fmaxf(areg[r].w + gvn.w, 0.f));
                    *(uint2*)(AsN + m * AS_STRH + k4 * 4) =
                        make_uint2(*(uint32_t*)&h01, *(uint32_t*)&h23);
                }
            }
            if (cg == 0)      asm volatile("cp.async.wait_group 2;" ::: "memory");
            else if (cg == 1) asm volatile("cp.async.wait_group 1;" ::: "memory");
            else if (cg == 2) asm volatile("cp.async.wait_group 0;" ::: "memory");
            __syncthreads();
            cg++;
        }

        #pragma unroll
        for (int mt = 0; mt < 2; mt++) {
            float s0 = 0.f, s1 = 0.f;
            #pragma unroll
            for (int nt = 0; nt < 8; nt++) {
                int n = n0w + nt * 8 + 2 * tig;
                float w0 = w3s[n], w1 = w3s[n + 1];
                float c0 = b2s[n], c1 = b2s[n + 1];
                s0 += fmaxf(acc[mt][nt][0] + c0, 0.f) * w0
                    + fmaxf(acc[mt][nt][1] + c1, 0.f) * w1;
                s1 += fmaxf(acc[mt][nt][2] + c0, 0.f) * w0
                    + fmaxf(acc[mt][nt][3] + c1, 0.f) * w1;
            }
            s0 += __shfl_xor_sync(0xffffffffu, s0, 1);
            s0 += __shfl_xor_sync(0xffffffffu, s0, 2);
            s1 += __shfl_xor_sync(0xffffffffu, s1, 1);
            s1 += __shfl_xor_sync(0xffffffffu, s1, 2);
            if (tig == 0) {
                red[(m0w + mt * 16 + g) * 4 + nw]     = s0;
                red[(m0w + mt * 16 + g + 8) * 4 + nw] = s1;
            }
        }
        #pragma unroll
        for (int mt = 0; mt < 2; mt++)
            #pragma unroll
            for (int nt = 0; nt < 8; nt++)
                #pragma unroll
                for (int q = 0; q < 4; q++) acc[mt][nt][q] = 0.f;
        __syncthreads();
        if (tid < 128) {
            float s = red[tid * 4] + red[tid * 4 + 1] + red[tid * 4 + 2] + red[tid * 4 + 3];
            g_scores[ii * NHW + jt * 128 + tid] = s + b3v;
        }
        __syncthreads();
    }
}

// ---------------------------------------------------------------------------
// finalize: register-cached row + shuffle reductions (2-stage)
// ---------------------------------------------------------------------------
__global__ __launch_bounds__(1024) void finalize_kernel(float* __restrict__ out) {
    const int i    = blockIdx.x;
    const int tid  = threadIdx.x;
    const int wid  = tid >> 5, lane = tid & 31;
    __shared__ float sred[32];
    __shared__ float sbc[2];
    const float* row = g_scores + i * NHW;

    float v[7];
    const bool has7 = (tid < NHW - 6 * 1024);
    float mx = -1e30f;
    #pragma unroll
    for (int k = 0; k < 6; k++) {
        v[k] = row[tid + k * 1024];
        mx = fmaxf(mx, v[k]);
    }
    if (has7) { v[6] = row[tid + 6 * 1024]; mx = fmaxf(mx, v[6]); }

    #pragma unroll
    for (int off = 16; off; off >>= 1)
        mx = fmaxf(mx, __shfl_xor_sync(0xffffffffu, mx, off));
    if (lane == 0) sred[wid] = mx;
    __syncthreads();
    if (wid == 0) {
        float m = sred[lane];
        #pragma unroll
        for (int off = 16; off; off >>= 1)
            m = fmaxf(m, __shfl_xor_sync(0xffffffffu, m, off));
        if (lane == 0) sbc[0] = m;
    }
    __syncthreads();
    mx = sbc[0];

    const int lo = i * HW2, hi = lo + HW2;
    float sum = 0.f;
    #pragma unroll
    for (int k = 0; k < 6; k++) {
        int jj = tid + k * 1024;
        if (jj < lo || jj >= hi) sum += __expf(v[k] - mx);
    }
    if (has7) {
        int jj = tid + 6 * 1024;
        if (jj < lo || jj >= hi) sum += __expf(v[6] - mx);
    }
    #pragma unroll
    for (int off = 16; off; off >>= 1)
        sum += __shfl_xor_sync(0xffffffffu, sum, off);
    if (lane == 0) sred[wid] = sum;
    __syncthreads();
    if (wid == 0) {
        float s = sred[lane];
        #pragma unroll
        for (int off = 16; off; off >>= 1)
            s += __shfl_xor_sync(0xffffffffu, s, off);
        if (lane == 0) sbc[1] = s;
    }
    __syncthreads();

    const float neg_mean = sbc[1] / (float)(NHW - HW2) + EPSC;
    const float lg = __logf(neg_mean);

    for (int p = tid; p < HW2; p += 1024)
        out[i * HW2 + p] = row[lo + p] - mx - lg;
}

// ---------------------------------------------------------------------------
extern "C" void kernel_launch(void* const* d_in, const int* in_sizes, int n_in,
                              void* d_out, int out_size) {
    const float* LF = (const float*)d_in[0];
    const float* GF = (const float*)d_in[1];
    const float* W1 = (const float*)d_in[2];
    const float* b1 = (const float*)d_in[3];
    const float* W2 = (const float*)d_in[4];
    const float* b2 = (const float*)d_in[5];
    const float* W3 = (const float*)d_in[6];
    const float* b3 = (const float*)d_in[7];
    float* out = (float*)d_out;

    cudaFuncSetAttribute(hloc_kernel, cudaFuncAttributeMaxDynamicSharedMemorySize, HL_SMEM);
    cudaFuncSetAttribute(score_mma, cudaFuncAttributeMaxDynamicSharedMemorySize, SM_TOTAL);

    prep0_kernel<<<272, 256>>>(GF, W1, b1, W2, W1 + (size_t)DGLB * HIDN);
    hloc_kernel<<<196, 256, HL_SMEM>>>(LF);
    score_mma<<<NCTA, 512, SM_TOTAL>>>(b2, W3, b3);
    finalize_kernel<<<NB, 1024>>>(out);
}

// round 16
// speedup vs baseline: 1.1325x; 1.1325x over previous
#include <cuda_runtime.h>
#include <cuda_fp16.h>
#include <cstdint>

// Problem constants
#define NB    32
#define CLOC  512
#define HW2   196
#define NHW   6272
#define DGLB  2048
#define HIDN  256
#define EPSC  1e-10f
#define NJT   49                    // j-tiles of 128
#define NTILE (NJT * NB)            // 1568 tiles
#define NCTA  148                   // persistent CTAs

// Scratch (device globals; no allocation allowed)
__device__ float    g_hloc[NHW * HIDN];      // 6.4 MB
__device__ float    g_hglb[NB * HIDN];
__device__ float    g_scores[NB * NHW];      // 0.8 MB
// W2 in mma-fragment order: pair id = ((ks*4 + nw)*8 + nt)*32 + lane
__device__ uint2    g_W2f[16 * 4 * 8 * 32];  // 128 KB

// ---------------------------------------------------------------------------
// helpers
// ---------------------------------------------------------------------------
__device__ __forceinline__ void mma16(float* c, const uint32_t* a,
                                      uint32_t b0, uint32_t b1) {
    asm volatile(
        "mma.sync.aligned.m16n8k16.row.col.f32.f16.f16.f32 "
        "{%0,%1,%2,%3}, {%4,%5,%6,%7}, {%8,%9}, {%0,%1,%2,%3};"
        : "+f"(c[0]), "+f"(c[1]), "+f"(c[2]), "+f"(c[3])
        : "r"(a[0]), "r"(a[1]), "r"(a[2]), "r"(a[3]), "r"(b0), "r"(b1));
}
__device__ __forceinline__ uint32_t smem_u32(const void* p) {
    uint32_t a;
    asm("{ .reg .u64 t; cvta.to.shared.u64 t, %1; cvt.u32.u64 %0, t; }" : "=r"(a) : "l"(p));
    return a;
}
__device__ __forceinline__ void cpa16(uint32_t dst, const void* src) {
    asm volatile("cp.async.ca.shared.global [%0], [%1], 16;" :: "r"(dst), "l"(src));
}
#define CPA_COMMIT() asm volatile("cp.async.commit_group;" ::: "memory")

// ---------------------------------------------------------------------------
// pre_kernel (256-thread blocks, dynamic smem), grid = 362:
//   blocks 0..97    -> hloc fp16 mma: BM=64, BN=256, BK=32 x 16 chunks
//   blocks 98..353  -> h_glb: (i = bb>>3, o-chunk = (bb&7)*32), K/8
//   blocks 354..361 -> pack W2 into fp16 fragment order
// hloc: 8 warps = 2m x 4n (warp 32m x 64n); acc[2][8][4] = 64 regs.
// A smem: 64 rows x 40 halves (bank-perfect) x2 buffers.
// B smem: [k2][n] half2, 16 k2-rows x 264 words x2 buffers.
// kstep order identical to R14 -> g_hloc bit-identical.
// ---------------------------------------------------------------------------
#define HA_HW   40                           // A stride in halves (20 words)
#define HA_B    (64 * HA_HW * 2)             // 5120 bytes per A buffer
#define HB_W    264                          // B stride in words
#define HB_B    (16 * HB_W * 4)              // 16896 bytes per B buffer
#define PRE_SMEM (2 * HA_B + 2 * HB_B)       // 44032 bytes

__global__ __launch_bounds__(256) void pre_kernel(const float* __restrict__ LF,
                                                  const float* __restrict__ W1loc,
                                                  const float* __restrict__ gf,
                                                  const float* __restrict__ W1,
                                                  const float* __restrict__ b1,
                                                  const float* __restrict__ W2) {
    extern __shared__ float dsm[];
    const int tid = threadIdx.x;
    const int bx  = blockIdx.x;

    if (bx < 98) {
        // ================= hloc via fp16 mma, BM=64 =================
        char* base = (char*)dsm;
        const int wid = tid >> 5, lid = tid & 31;
        const int g   = lid >> 2, tig = lid & 3;
        const int m0w = (wid & 1) * 32;
        const int n0w = (wid >> 1) * 64;
        const int j0  = bx * 64;

        // A build map: row = tid&63, akq = tid>>6 -> halves akq*8..akq*8+7
        const int arow = tid & 63;
        const int akq  = tid >> 6;
        const int j    = j0 + arow;
        const int n_   = j / HW2;
        const int pos  = j % HW2;
        const size_t abase = (size_t)n_ * CLOC * HW2 + pos;
        // B build map: bn4 = tid&63 (n = bn4*4), bkb = tid>>6 (k2 rows bkb+4r)
        const int bn4 = tid & 63;
        const int bkb = tid >> 6;

        float acc[2][8][4];
        #pragma unroll
        for (int mt = 0; mt < 2; mt++)
            #pragma unroll
            for (int nt = 0; nt < 8; nt++)
                #pragma unroll
                for (int q = 0; q < 4; q++) acc[mt][nt][q] = 0.f;

        // ---- build chunk 0 into buffer 0 ----
        {
            __half* A0 = (__half*)base;
            uint32_t* B0 = (uint32_t*)(base + 2 * HA_B);
            float f[8];
            #pragma unroll
            for (int q = 0; q < 8; q++)
                f[q] = LF[abase + (size_t)(akq * 8 + q) * HW2];
            __half2 h0 = __floats2half2_rn(f[0], f[1]);
            __half2 h1 = __floats2half2_rn(f[2], f[3]);
            __half2 h2 = __floats2half2_rn(f[4], f[5]);
            __half2 h3 = __floats2half2_rn(f[6], f[7]);
            *(uint4*)(A0 + arow * HA_HW + akq * 8) =
                make_uint4(*(uint32_t*)&h0, *(uint32_t*)&h1,
                           *(uint32_t*)&h2, *(uint32_t*)&h3);
            #pragma unroll
            for (int r = 0; r < 4; r++) {
                int k2 = bkb + r * 4;                 // local k2 row
                float4 va = *(const float4*)&W1loc[(size_t)(2 * k2)     * HIDN + bn4 * 4];
                float4 vb = *(const float4*)&W1loc[(size_t)(2 * k2 + 1) * HIDN + bn4 * 4];
                __half2 p0 = __floats2half2_rn(va.x, vb.x);
                __half2 p1 = __floats2half2_rn(va.y, vb.y);
                __half2 p2 = __floats2half2_rn(va.z, vb.z);
                __half2 p3 = __floats2half2_rn(va.w, vb.w);
                uint32_t* d = B0 + k2 * HB_W + bn4 * 4;
                d[0] = *(uint32_t*)&p0; d[1] = *(uint32_t*)&p1;
                d[2] = *(uint32_t*)&p2; d[3] = *(uint32_t*)&p3;
            }
        }
        __syncthreads();

        for (int c = 0; c < 16; c++) {
            const int pb = c & 1, nb = pb ^ 1;
            const uint32_t* AsU = (const uint32_t*)(base + pb * HA_B);
            const uint32_t* BsU = (const uint32_t*)(base + 2 * HA_B + pb * HB_B);

            // prefetch next chunk to registers
            float aR[8];
            float4 bRa[4], bRb[4];
            if (c < 15) {
                const int kb = (c + 1) * 32;
                #pragma unroll
                for (int q = 0; q < 8; q++)
                    aR[q] = LF[abase + (size_t)(kb + akq * 8 + q) * HW2];
                #pragma unroll
                for (int r = 0; r < 4; r++) {
                    int gk = kb + 2 * (bkb + r * 4);
                    bRa[r] = *(const float4*)&W1loc[(size_t)gk       * HIDN + bn4 * 4];
                    bRb[r] = *(const float4*)&W1loc[(size_t)(gk + 1) * HIDN + bn4 * 4];
                }
            }

            // mma: 2 k16 steps, 2mt x 8nt
            #pragma unroll
            for (int s = 0; s < 2; s++) {
                const int kw = s * 8;
                uint32_t a[2][4];
                #pragma unroll
                for (int mt = 0; mt < 2; mt++) {
                    int mr = m0w + mt * 16 + g;
                    a[mt][0] = AsU[mr * 20 + kw + tig];
                    a[mt][1] = AsU[(mr + 8) * 20 + kw + tig];
                    a[mt][2] = AsU[mr * 20 + kw + tig + 4];
                    a[mt][3] = AsU[(mr + 8) * 20 + kw + tig + 4];
                }
                #pragma unroll
                for (int nt = 0; nt < 8; nt++) {
                    int nc = n0w + nt * 8 + g;
                    uint32_t b0 = BsU[(s * 8 + tig) * HB_W + nc];
                    uint32_t b1 = BsU[(s * 8 + tig + 4) * HB_W + nc];
                    mma16(acc[0][nt], a[0], b0, b1);
                    mma16(acc[1][nt], a[1], b0, b1);
                }
            }

            // store prefetched chunk into other buffer
            if (c < 15) {
                __half* AN = (__half*)(base + nb * HA_B);
                uint32_t* BN = (uint32_t*)(base + 2 * HA_B + nb * HB_B);
                __half2 h0 = __floats2half2_rn(aR[0], aR[1]);
                __half2 h1 = __floats2half2_rn(aR[2], aR[3]);
                __half2 h2 = __floats2half2_rn(aR[4], aR[5]);
                __half2 h3 = __floats2half2_rn(aR[6], aR[7]);
                *(uint4*)(AN + arow * HA_HW + akq * 8) =
                    make_uint4(*(uint32_t*)&h0, *(uint32_t*)&h1,
                               *(uint32_t*)&h2, *(uint32_t*)&h3);
                #pragma unroll
                for (int r = 0; r < 4; r++) {
                    int k2 = bkb + r * 4;
                    __half2 p0 = __floats2half2_rn(bRa[r].x, bRb[r].x);
                    __half2 p1 = __floats2half2_rn(bRa[r].y, bRb[r].y);
                    __half2 p2 = __floats2half2_rn(bRa[r].z, bRb[r].z);
                    __half2 p3 = __floats2half2_rn(bRa[r].w, bRb[r].w);
                    uint32_t* d = BN + k2 * HB_W + bn4 * 4;
                    d[0] = *(uint32_t*)&p0; d[1] = *(uint32_t*)&p1;
                    d[2] = *(uint32_t*)&p2; d[3] = *(uint32_t*)&p3;
                }
                __syncthreads();
            }
        }

        // epilogue: write fp32 h_loc
        #pragma unroll
        for (int mt = 0; mt < 2; mt++) {
            int row0 = j0 + m0w + mt * 16 + g;
            #pragma unroll
            for (int nt = 0; nt < 8; nt++) {
                int ncol = n0w + nt * 8 + 2 * tig;
                *(float2*)&g_hloc[(size_t)row0 * HIDN + ncol] =
                    make_float2(acc[mt][nt][0], acc[mt][nt][1]);
                *(float2*)&g_hloc[(size_t)(row0 + 8) * HIDN + ncol] =
                    make_float2(acc[mt][nt][2], acc[mt][nt][3]);
            }
        }
    } else if (bx < 354) {
        // ================= h_glb =================
        float* red = dsm;                    // 256 floats
        const int bb  = bx - 98;
        const int i   = bb >> 3;
        const int o0  = (bb & 7) * 32;
        const int o   = o0 + (tid & 31);
        const int kq  = tid >> 5;            // 0..7
        const float* g = gf + i * DGLB + kq * 256;
        const float* w = W1 + (size_t)(kq * 256) * HIDN + o;
        float s0 = 0.f, s1 = 0.f;
        #pragma unroll 8
        for (int k = 0; k < 256; k += 2) {
            s0 += g[k]     * w[(size_t)k * HIDN];
            s1 += g[k + 1] * w[(size_t)(k + 1) * HIDN];
        }
        red[tid] = s0 + s1;
        __syncthreads();
        if (tid < 32) {
            float s = 0.f;
            #pragma unroll
            for (int q = 0; q < 8; q++) s += red[q * 32 + tid];
            g_hglb[i * HIDN + o0 + tid] = s + b1[o0 + tid];
        }
    } else {
        // ================= W2 fragment pack =================
        const int pid0 = ((bx - 354) * 256 + tid) * 8;
        #pragma unroll
        for (int q = 0; q < 8; q++) {
            int id   = pid0 + q;
            int lane = id & 31;
            int nt   = (id >> 5) & 7;
            int nwp  = (id >> 8) & 3;
            int ks   = id >> 10;
            int gq   = lane >> 2, tg = lane & 3;
            int n    = nwp * 64 + nt * 8 + gq;
            int k0   = ks * 16 + 2 * tg;
            __half2 w0 = __floats2half2_rn(W2[(size_t)k0 * HIDN + n],
                                           W2[(size_t)(k0 + 1) * HIDN + n]);
            __half2 w1 = __floats2half2_rn(W2[(size_t)(k0 + 8) * HIDN + n],
                                           W2[(size_t)(k0 + 9) * HIDN + n]);
            g_W2f[id] = make_uint2(*(uint32_t*)&w0, *(uint32_t*)&w1);
        }
    }
}

// ---------------------------------------------------------------------------
// PERSISTENT score kernel (UNCHANGED from R12-R14): 148 CTAs, 512 threads.
// ---------------------------------------------------------------------------
#define AS_STRH  72                                 // halves per A row (36 words)
#define AS_BYTES (128 * AS_STRH * 2)                // 18432
#define BCHUNK   32768
#define AS_OFF   0
#define BS_OFF   (2 * AS_BYTES)                     // 36864
#define B2_OFF   (BS_OFF + 4 * BCHUNK)              // 167936
#define W3_OFF   (B2_OFF + 1024)
#define RED_OFF  (W3_OFF + 1024)
#define SM_TOTAL (RED_OFF + 128 * 4 * 4)            // 172032

__global__ __launch_bounds__(512, 1) void score_mma(const float* __restrict__ b2,
                                                    const float* __restrict__ W3,
                                                    const float* __restrict__ b3p) {
    extern __shared__ char smem[];
    float* b2s = (float*)(smem + B2_OFF);
    float* w3s = (float*)(smem + W3_OFF);
    float* red = (float*)(smem + RED_OFF);
    const uint32_t sbase = smem_u32(smem);

    const int tid = threadIdx.x;
    const int wid = tid >> 5, lid = tid & 31;
    const int g   = lid >> 2, tig = lid & 3;
    const int m0w = (wid & 3) * 32;
    const int nw  = wid >> 2;
    const int n0w = nw * 64;

    {
        const char* bsrc = (const char*)g_W2f;
        #pragma unroll
        for (int cg2 = 0; cg2 < 4; cg2++) {
            #pragma unroll
            for (int r = 0; r < 4; r++) {
                int off = cg2 * BCHUNK + (tid + r * 512) * 16;
                cpa16(sbase + BS_OFF + off, bsrc + off);
            }
            CPA_COMMIT();
        }
    }

    if (tid < 256) { b2s[tid] = b2[tid]; w3s[tid] = W3[tid]; }
    const float b3v = b3p[0];

    const int k4   = tid & 15;
    const int mrow = tid >> 4;

    float acc[2][8][4];
    #pragma unroll
    for (int mt = 0; mt < 2; mt++)
        #pragma unroll
        for (int nt = 0; nt < 8; nt++)
            #pragma unroll
            for (int q = 0; q < 4; q++) acc[mt][nt][q] = 0.f;

    {
        const int t0 = blockIdx.x;
        const float* hl = g_hloc + (size_t)(t0 % NJT) * 128 * HIDN;
        const float* gb = g_hglb + (t0 / NJT) * HIDN;
        float4 gv = *(const float4*)(gb + k4 * 4);
        __half* As0 = (__half*)(smem + AS_OFF);
        #pragma unroll
        for (int r = 0; r < 4; r++) {
            int m = mrow + r * 32;
            float4 v = *(const float4*)(hl + (size_t)m * HIDN + k4 * 4);
            __half2 h01 = __floats2half2_rn(fmaxf(v.x + gv.x, 0.f), fmaxf(v.y + gv.y, 0.f));
            __half2 h23 = __floats2half2_rn(fmaxf(v.z + gv.z, 0.f), fmaxf(v.w + gv.w, 0.f));
            *(uint2*)(As0 + m * AS_STRH + k4 * 4) =
                make_uint2(*(uint32_t*)&h01, *(uint32_t*)&h23);
        }
        asm volatile("cp.async.wait_group 3;" ::: "memory");
        __syncthreads();
    }

    const uint2* BsP = (const uint2*)(smem + BS_OFF);
    int cg = 0;

    for (int t = blockIdx.x; t < NTILE; t += NCTA) {
        const int jt = t % NJT, ii = t / NJT;

        for (int c = 0; c < 4; c++) {
            const int pb = cg & 1, nb = pb ^ 1;
            const uint32_t* AsU = (const uint32_t*)(smem + AS_OFF + pb * AS_BYTES);

            const bool hn = (c < 3) || (t + NCTA < NTILE);
            float4 areg[4];
            float4 gvn;
            if (hn) {
                const int t2 = (c < 3) ? t : t + NCTA;
                const int c2 = (c < 3) ? c + 1 : 0;
                const float* hl2 = g_hloc + (size_t)(t2 % NJT) * 128 * HIDN;
                const float* gb2 = g_hglb + (t2 / NJT) * HIDN;
                const int kb2 = c2 * 64;
                gvn = *(const float4*)(gb2 + kb2 + k4 * 4);
                #pragma unroll
                for (int r = 0; r < 4; r++) {
                    int m = mrow + r * 32;
                    areg[r] = *(const float4*)(hl2 + (size_t)m * HIDN + kb2 + k4 * 4);
                }
            }

            #pragma unroll
            for (int kk = 0; kk < 4; kk++) {
                const int kw = kk * 8;
                const int ks = c * 4 + kk;
                uint32_t a[2][4];
                #pragma unroll
                for (int mt = 0; mt < 2; mt++) {
                    int mr = m0w + mt * 16 + g;
                    a[mt][0] = AsU[mr * 36 + kw + tig];
                    a[mt][1] = AsU[(mr + 8) * 36 + kw + tig];
                    a[mt][2] = AsU[mr * 36 + kw + tig + 4];
                    a[mt][3] = AsU[(mr + 8) * 36 + kw + tig + 4];
                }
                #pragma unroll
                for (int nt = 0; nt < 8; nt++) {
                    uint2 bw = BsP[((ks * 4 + nw) * 8 + nt) * 32 + lid];
                    mma16(acc[0][nt], a[0], bw.x, bw.y);
                    mma16(acc[1][nt], a[1], bw.x, bw.y);
                }
            }

            if (hn) {
                __half* AsN = (__half*)(smem + AS_OFF + nb * AS_BYTES);
                #pragma unroll
                for (int r = 0; r < 4; r++) {
                    int m = mrow + r * 32;
                    __half2 h01 = __floats2half2_rn(fmaxf(areg[r].x + gvn.x, 0.f),
                                                    fmaxf(areg[r].y + gvn.y, 0.f));
                    __half2 h23 = __floats2half2_rn(fmaxf(areg[r].z + gvn.z, 0.f),
                                                    fmaxf(areg[r].w + gvn.w, 0.f));
                    *(uint2*)(AsN + m * AS_STRH + k4 * 4) =
                        make_uint2(*(uint32_t*)&h01, *(uint32_t*)&h23);
                }
            }
            if (cg == 0)      asm volatile("cp.async.wait_group 2;" ::: "memory");
            else if (cg == 1) asm volatile("cp.async.wait_group 1;" ::: "memory");
            else if (cg == 2) asm volatile("cp.async.wait_group 0;" ::: "memory");
            __syncthreads();
            cg++;
        }

        #pragma unroll
        for (int mt = 0; mt < 2; mt++) {
            float s0 = 0.f, s1 = 0.f;
            #pragma unroll
            for (int nt = 0; nt < 8; nt++) {
                int n = n0w + nt * 8 + 2 * tig;
                float w0 = w3s[n], w1 = w3s[n + 1];
                float c0 = b2s[n], c1 = b2s[n + 1];
                s0 += fmaxf(acc[mt][nt][0] + c0, 0.f) * w0
                    + fmaxf(acc[mt][nt][1] + c1, 0.f) * w1;
                s1 += fmaxf(acc[mt][nt][2] + c0, 0.f) * w0
                    + fmaxf(acc[mt][nt][3] + c1, 0.f) * w1;
            }
            s0 += __shfl_xor_sync(0xffffffffu, s0, 1);
            s0 += __shfl_xor_sync(0xffffffffu, s0, 2);
            s1 += __shfl_xor_sync(0xffffffffu, s1, 1);
            s1 += __shfl_xor_sync(0xffffffffu, s1, 2);
            if (tig == 0) {
                red[(m0w + mt * 16 + g) * 4 + nw]     = s0;
                red[(m0w + mt * 16 + g + 8) * 4 + nw] = s1;
            }
        }
        #pragma unroll
        for (int mt = 0; mt < 2; mt++)
            #pragma unroll
            for (int nt = 0; nt < 8; nt++)
                #pragma unroll
                for (int q = 0; q < 4; q++) acc[mt][nt][q] = 0.f;
        __syncthreads();
        if (tid < 128) {
            float s = red[tid * 4] + red[tid * 4 + 1] + red[tid * 4 + 2] + red[tid * 4 + 3];
            g_scores[ii * NHW + jt * 128 + tid] = s + b3v;
        }
        __syncthreads();
    }
}

// ---------------------------------------------------------------------------
// finalize: register-cached row + shuffle reductions (2-stage)
// ---------------------------------------------------------------------------
__global__ __launch_bounds__(1024) void finalize_kernel(float* __restrict__ out) {
    const int i    = blockIdx.x;
    const int tid  = threadIdx.x;
    const int wid  = tid >> 5, lane = tid & 31;
    __shared__ float sred[32];
    __shared__ float sbc[2];
    const float* row = g_scores + i * NHW;

    float v[7];
    const bool has7 = (tid < NHW - 6 * 1024);
    float mx = -1e30f;
    #pragma unroll
    for (int k = 0; k < 6; k++) {
        v[k] = row[tid + k * 1024];
        mx = fmaxf(mx, v[k]);
    }
    if (has7) { v[6] = row[tid + 6 * 1024]; mx = fmaxf(mx, v[6]); }

    #pragma unroll
    for (int off = 16; off; off >>= 1)
        mx = fmaxf(mx, __shfl_xor_sync(0xffffffffu, mx, off));
    if (lane == 0) sred[wid] = mx;
    __syncthreads();
    if (wid == 0) {
        float m = sred[lane];
        #pragma unroll
        for (int off = 16; off; off >>= 1)
            m = fmaxf(m, __shfl_xor_sync(0xffffffffu, m, off));
        if (lane == 0) sbc[0] = m;
    }
    __syncthreads();
    mx = sbc[0];

    const int lo = i * HW2, hi = lo + HW2;
    float sum = 0.f;
    #pragma unroll
    for (int k = 0; k < 6; k++) {
        int jj = tid + k * 1024;
        if (jj < lo || jj >= hi) sum += __expf(v[k] - mx);
    }
    if (has7) {
        int jj = tid + 6 * 1024;
        if (jj < lo || jj >= hi) sum += __expf(v[6] - mx);
    }
    #pragma unroll
    for (int off = 16; off; off >>= 1)
        sum += __shfl_xor_sync(0xffffffffu, sum, off);
    if (lane == 0) sred[wid] = sum;
    __syncthreads();
    if (wid == 0) {
        float s = sred[lane];
        #pragma unroll
        for (int off = 16; off; off >>= 1)
            s += __shfl_xor_sync(0xffffffffu, s, off);
        if (lane == 0) sbc[1] = s;
    }
    __syncthreads();

    const float neg_mean = sbc[1] / (float)(NHW - HW2) + EPSC;
    const float lg = __logf(neg_mean);

    for (int p = tid; p < HW2; p += 1024)
        out[i * HW2 + p] = row[lo + p] - mx - lg;
}

// ---------------------------------------------------------------------------
extern "C" void kernel_launch(void* const* d_in, const int* in_sizes, int n_in,
                              void* d_out, int out_size) {
    const float* LF = (const float*)d_in[0];
    const float* GF = (const float*)d_in[1];
    const float* W1 = (const float*)d_in[2];
    const float* b1 = (const float*)d_in[3];
    const float* W2 = (const float*)d_in[4];
    const float* b2 = (const float*)d_in[5];
    const float* W3 = (const float*)d_in[6];
    const float* b3 = (const float*)d_in[7];
    float* out = (float*)d_out;

    cudaFuncSetAttribute(pre_kernel, cudaFuncAttributeMaxDynamicSharedMemorySize, PRE_SMEM);
    cudaFuncSetAttribute(score_mma, cudaFuncAttributeMaxDynamicSharedMemorySize, SM_TOTAL);

    pre_kernel<<<362, 256, PRE_SMEM>>>(LF, W1 + (size_t)DGLB * HIDN, GF, W1, b1, W2);
    score_mma<<<NCTA, 512, SM_TOTAL>>>(b2, W3, b3);
    finalize_kernel<<<NB, 1024>>>(out);
}